// round 14
// baseline (speedup 1.0000x reference)
#include <cuda_runtime.h>

#define TPB   288
#define NGRID 144          // g0:32  g1-g3:32 each  g4:16
#define WID   1024
#define HID   256
#define NST   17
#define NY    273
#define T_N   64
#define SUB   8
#define NSTAGE 2016

// ---------------- global scratch (no allocs) ----------------
__device__ __align__(16) float g_zb[4][WID];   // z0..z3 (single-buffered, ring-safe)
__device__ __align__(16) float g_dh[HID];      // final-layer output (scaled)
__device__ unsigned g_lnk[5 * 4 * 32];         // 5 links x 4 sub-counters (128B apart)

__device__ __forceinline__ unsigned ld_acq(unsigned* p) {
    unsigned v;
    asm volatile("ld.acquire.gpu.global.u32 %0, [%1];" : "=r"(v) : "l"(p) : "memory");
    return v;
}
__device__ __forceinline__ void red_rel(unsigned* p) {
    asm volatile("red.release.gpu.global.add.u32 [%0], %1;" :: "l"(p), "r"(1u) : "memory");
}

// thread0-only acquire poll of a link's 4 sub-counters (pipelined loads),
// followed by CTA bar at the call site. ONE poller per CTA — poll storms
// (R6/R13) are proven fatal.
__device__ __forceinline__ void wait4(int l, unsigned tgt) {
    unsigned* p = &g_lnk[l * 4 * 32];
    unsigned s;
    do {
        s = ld_acq(p) + ld_acq(p + 32) + ld_acq(p + 64) + ld_acq(p + 96);
    } while ((int)(s - tgt) < 0);
}

__device__ __forceinline__ float softplus_f(float v) {
    return fmaxf(v, 0.f) + log1pf(expf(-fabsf(v)));
}
__device__ __forceinline__ float warp_sum(float a) {
#pragma unroll
    for (int o = 16; o > 0; o >>= 1) a += __shfl_xor_sync(0xffffffffu, a, o);
    return a;
}
// 4-row reduce: lane j (j<4) holds full sum of row j
__device__ __forceinline__ float reduce4(float a0, float a1, float a2, float a3,
                                         int lane) {
    a0 += __shfl_xor_sync(0xffffffffu, a0, 1);
    a1 += __shfl_xor_sync(0xffffffffu, a1, 1);
    a2 += __shfl_xor_sync(0xffffffffu, a2, 1);
    a3 += __shfl_xor_sync(0xffffffffu, a3, 1);
    a0 += __shfl_xor_sync(0xffffffffu, a0, 2);
    a1 += __shfl_xor_sync(0xffffffffu, a1, 2);
    a2 += __shfl_xor_sync(0xffffffffu, a2, 2);
    a3 += __shfl_xor_sync(0xffffffffu, a3, 2);
    float v = (lane & 2) ? ((lane & 1) ? a3 : a2) : ((lane & 1) ? a1 : a0);
    v += __shfl_xor_sync(0xffffffffu, v, 4);
    v += __shfl_xor_sync(0xffffffffu, v, 8);
    v += __shfl_xor_sync(0xffffffffu, v, 16);
    return v;
}
// 2-row reduce: lane j (j<2) holds full sum of row j
__device__ __forceinline__ float reduce2(float a0, float a1, int lane) {
    a0 += __shfl_xor_sync(0xffffffffu, a0, 1);
    a1 += __shfl_xor_sync(0xffffffffu, a1, 1);
    float v = (lane & 1) ? a1 : a0;
    v += __shfl_xor_sync(0xffffffffu, v, 2);
    v += __shfl_xor_sync(0xffffffffu, v, 4);
    v += __shfl_xor_sync(0xffffffffu, v, 8);
    v += __shfl_xor_sync(0xffffffffu, v, 16);
    return v;
}

__global__ void reset_kernel() {
    for (int i = 0; i < 20; i++) g_lnk[i * 32] = 0u;
}

__global__ void __launch_bounds__(TPB, 1)
ode_kernel(const float* __restrict__ ts,  const float* __restrict__ W0,
           const float* __restrict__ b0,  const float* __restrict__ Wh,
           const float* __restrict__ bh,  const float* __restrict__ Wl,
           const float* __restrict__ bl,  const float* __restrict__ bW,
           const float* __restrict__ bb,  const float* __restrict__ hvec,
           const float* __restrict__ scale, const float* __restrict__ y0log,
           float* __restrict__ out)
{
    const int tid  = threadIdx.x;
    const int b    = blockIdx.x;
    const int warp = tid >> 5;
    const int lane = tid & 31;

    if (b < 32) {
        // ══════════════ GROUP 0: x-build + layer0 + SEIR + state owner ══════════════
        __shared__ float sx[288];      // MLP input [h(256) | state(17) | pad]
        __shared__ float sk[NST];      // SEIR slopes (computed locally per block)
        __shared__ float sbias[32];
        __shared__ float sbw[256];
        __shared__ float sbb_s[1];
        const int lb = b;

        float w0r[4][9];
#pragma unroll
        for (int r = 0; r < 4; r++)
#pragma unroll
            for (int i = 0; i < 9; i++) {
                int col = lane + 32 * i;
                int row = lb * 32 + warp * 4 + r;
                w0r[r][i] = (warp < 8 && col < 273)
                            ? __ldg(&W0[row * 273 + col]) : 0.f;
            }
        if (tid < 32) sbias[tid] = b0[lb * 32 + tid];
        for (int i = tid; i < 256; i += TPB) sbw[i] = bW[i];
        if (tid == 0) sbb_s[0] = bb[0];
        if (tid >= NY && tid < 288) sx[tid] = 0.f;   // pad stays 0

        float y = 0.f, k1 = 0.f, k2 = 0.f, k3 = 0.f;
        if (tid < NY) {
            if (tid < NST) {
                float m = -1e30f;
                for (int i = 0; i < NST; i++) m = fmaxf(m, __ldg(&y0log[i]));
                float s = 0.f;
                for (int i = 0; i < NST; i++) s += expf(__ldg(&y0log[i]) - m);
                y = expf(__ldg(&y0log[tid]) - m) / s;
            } else {
                y = __ldg(&hvec[tid - NST]);
            }
        }
        __syncthreads();

        if (b == 0 && tid < NY) {                  // output row 0
            if (tid < NST) out[tid] = y;
            else           out[T_N * NST + (tid - NST)] = y;
        }

        for (int iv = 0; iv < T_N - 1; ++iv) {
            float dt  = (__ldg(&ts[iv + 1]) - __ldg(&ts[iv])) * (1.f / (float)SUB);
            float dt6 = dt * (1.f / 6.f);
            for (int ss = 0; ss < SUB; ++ss) {
                const unsigned base = 4u * (unsigned)(iv * SUB + ss);
#pragma unroll
                for (int st = 0; st < 4; ++st) {
                    const unsigned p = base + st;
                    if (st > 0) {
                        if (tid == 0) wait4(4, 128u * p);
                        __syncthreads();
                    }
                    // ---- x-build: k[st-1] = [sk (local smem), g_dh (L2)] ----
                    if (tid < NY) {
                        float xv = y;
                        if (st > 0) {
                            float kp = (tid < NST) ? sk[tid]
                                                   : __ldcg(&g_dh[tid - NST]);
                            if (st == 1) k1 = kp;
                            else if (st == 2) k2 = kp;
                            else k3 = kp;
                            xv = fmaf((st == 3) ? dt : 0.5f * dt, kp, y);
                        }
                        sx[(tid < NST) ? (HID + tid) : (tid - NST)] = xv;
                    }
                    __syncthreads();

                    if (warp < 8) {
                        // layer 0: 4 rows per warp, per-warp publish
                        float a0 = 0.f, a1 = 0.f, a2 = 0.f, a3 = 0.f;
#pragma unroll
                        for (int i = 0; i < 9; i++) {
                            float xv = sx[lane + 32 * i];
                            a0 = fmaf(w0r[0][i], xv, a0);
                            a1 = fmaf(w0r[1][i], xv, a1);
                            a2 = fmaf(w0r[2][i], xv, a2);
                            a3 = fmaf(w0r[3][i], xv, a3);
                        }
                        float v = reduce4(a0, a1, a2, a3, lane);
                        if (lane < 4)
                            __stcg(&g_zb[0][lb * 32 + warp * 4 + lane],
                                   softplus_f(v + sbias[warp * 4 + lane]));
                        __syncwarp();
                        if (lane == 0) red_rel(&g_lnk[(0 * 4 + (warp & 3)) * 32]);
                    } else {
                        // ---- SEIR (local to every g0 block) ----
                        float t = 0.f;
#pragma unroll
                        for (int i = 0; i < 8; i++) {
                            int k = lane + 32 * i;
                            t = fmaf(sbw[k], sx[k], t);
                        }
                        t = warp_sum(t);
                        if (lane == 0) {
                            float bb1 = 8.f / (1.f + expf(-(t + sbb_s[0]))) + 25.f;
                            const float MU   = (float)(0.041 / 12.0);
                            const float XI   = (float)(13.0 / 12.0);
                            const float XIMU = (float)(13.0 / 12.0 + 0.041 / 12.0);
                            const float MUSG = (float)(0.041 / 12.0 + 91.0 / 12.0);
                            const float SG   = (float)(91.0 / 12.0);
                            const float NU   = (float)(36.0 / 12.0);
                            const float NUMU = (float)(36.0 / 12.0 + 0.041 / 12.0);
                            const float MUGA = (float)(0.041 / 12.0 + 1.8 / 12.0);
                            const float GA   = (float)(1.8 / 12.0);
                            const float* s_ = &sx[HID];
                            float M  = s_[0],  S1 = s_[1],  E1 = s_[2],  E2 = s_[3];
                            float E3 = s_[4],  E4 = s_[5],  I1 = s_[6],  I2 = s_[7];
                            float I3 = s_[8],  I4 = s_[9],  R1 = s_[10], R2 = s_[11];
                            float R3 = s_[12], R4 = s_[13], S2 = s_[14], S3 = s_[15];
                            float S4 = s_[16];
                            float I = I1 + I2 + I3 + I4;
                            float R = R1 + R2 + R3 + R4;
                            float bb2 = 0.5f * bb1, bb3 = 0.35f * bb1, bb4 = 0.25f * bb1;
                            sk[0]  = R * MU - XIMU * M;
                            sk[1]  = MU * (1.f - R) + XI * M - MU * S1 - bb1 * I * S1;
                            sk[2]  = bb1 * I * S1 - MUSG * E1;
                            sk[3]  = bb2 * I * S2 - MUSG * E2;
                            sk[4]  = bb3 * I * S3 - MUSG * E3;
                            sk[5]  = bb4 * I * S4 - MUSG * E4;
                            sk[6]  = SG * E1 - NUMU * I1;
                            sk[7]  = SG * E2 - NUMU * I2;
                            sk[8]  = SG * E3 - NUMU * I3;
                            sk[9]  = SG * E4 - NUMU * I4;
                            sk[10] = NU * I1 - MUGA * R1;
                            sk[11] = NU * I2 - MUGA * R2;
                            sk[12] = NU * I3 - MUGA * R3;
                            sk[13] = NU * I4 - MUGA * R4;
                            sk[14] = GA * R1 - MU * S2 - bb2 * I * S2;
                            sk[15] = GA * R2 - MU * S3 - bb3 * I * S3;
                            sk[16] = GA * (R3 + R4) - MU * S4 - bb4 * I * S4;
                        }
                        __syncwarp();
                    }
                } // st

                // ---- substep boundary: RK combine ----
                if (tid == 0) wait4(4, 128u * (base + 4u));
                __syncthreads();
                if (tid < NY) {
                    float k4 = (tid < NST) ? sk[tid] : __ldcg(&g_dh[tid - NST]);
                    y = fmaf(dt6, k1 + 2.f * (k2 + k3) + k4, y);
                }
            } // ss

            if (b == 0 && tid < NY) {
                if (tid < NST) out[(iv + 1) * NST + tid] = y;
                else           out[T_N * NST + (iv + 1) * HID + (tid - NST)] = y;
            }
        } // iv

    } else if (b < 128) {
        // ══════════ GROUPS 1-3: hidden layers (thread0 poll, direct reg fetch) ══════════
        const int hl = (b >> 5) - 1;
        const int lb = b & 31;
        if (warp >= 8) return;           // 8 compute warps remain (bar counts them)
        float4 wt[4][8];
#pragma unroll
        for (int r = 0; r < 4; r++)
#pragma unroll
            for (int i = 0; i < 8; i++)
                wt[r][i] = __ldg((const float4*)&Wh[((hl * WID) + (lb * 32 + warp * 4 + r))
                                                    * WID + lane * 4 + 128 * i]);
        float breg = (lane < 4) ? __ldg(&bh[hl * WID + lb * 32 + warp * 4 + lane]) : 0.f;

        for (unsigned it = 1; it <= NSTAGE; ++it) {
            if (tid == 0) wait4(hl, 256u * it);
            __syncthreads();
            float a0 = 0.f, a1 = 0.f, a2 = 0.f, a3 = 0.f;
#pragma unroll
            for (int i = 0; i < 8; i++) {
                float4 z = __ldcg((const float4*)&g_zb[hl][(lane + 32 * i) * 4]);
                float4 q;
                q = wt[0][i];
                a0 = fmaf(q.x, z.x, a0); a0 = fmaf(q.y, z.y, a0);
                a0 = fmaf(q.z, z.z, a0); a0 = fmaf(q.w, z.w, a0);
                q = wt[1][i];
                a1 = fmaf(q.x, z.x, a1); a1 = fmaf(q.y, z.y, a1);
                a1 = fmaf(q.z, z.z, a1); a1 = fmaf(q.w, z.w, a1);
                q = wt[2][i];
                a2 = fmaf(q.x, z.x, a2); a2 = fmaf(q.y, z.y, a2);
                a2 = fmaf(q.z, z.z, a2); a2 = fmaf(q.w, z.w, a2);
                q = wt[3][i];
                a3 = fmaf(q.x, z.x, a3); a3 = fmaf(q.y, z.y, a3);
                a3 = fmaf(q.z, z.z, a3); a3 = fmaf(q.w, z.w, a3);
            }
            float v = reduce4(a0, a1, a2, a3, lane);
            if (lane < 4)
                __stcg(&g_zb[hl + 1][lb * 32 + warp * 4 + lane],
                       softplus_f(v + breg));
            __syncwarp();
            if (lane == 0) red_rel(&g_lnk[((hl + 1) * 4 + (warp & 3)) * 32]);
        }

    } else {
        // ══════════ GROUP 4: final layer (thread0 poll, direct reg fetch) ══════════
        const int lb = b - 128;
        if (warp >= 8) return;
        float4 wt[2][8];
#pragma unroll
        for (int r = 0; r < 2; r++)
#pragma unroll
            for (int i = 0; i < 8; i++)
                wt[r][i] = __ldg((const float4*)&Wl[(lb * 16 + warp * 2 + r) * WID
                                                    + lane * 4 + 128 * i]);
        float breg = (lane < 2) ? __ldg(&bl[lb * 16 + warp * 2 + lane]) : 0.f;
        const float scl = __ldg(&scale[0]);

        for (unsigned it = 1; it <= NSTAGE; ++it) {
            if (tid == 0) wait4(3, 256u * it);
            __syncthreads();
            float a0 = 0.f, a1 = 0.f;
#pragma unroll
            for (int i = 0; i < 8; i++) {
                float4 z = __ldcg((const float4*)&g_zb[3][(lane + 32 * i) * 4]);
                float4 q;
                q = wt[0][i];
                a0 = fmaf(q.x, z.x, a0); a0 = fmaf(q.y, z.y, a0);
                a0 = fmaf(q.z, z.z, a0); a0 = fmaf(q.w, z.w, a0);
                q = wt[1][i];
                a1 = fmaf(q.x, z.x, a1); a1 = fmaf(q.y, z.y, a1);
                a1 = fmaf(q.z, z.z, a1); a1 = fmaf(q.w, z.w, a1);
            }
            float v = reduce2(a0, a1, lane);
            if (lane < 2) {
                float u = tanhf(0.01f * (v + breg));
                __stcg(&g_dh[lb * 16 + warp * 2 + lane], scl * u);
            }
            __syncwarp();
            if (lane == 0) red_rel(&g_lnk[(4 * 4 + (warp & 3)) * 32]);
        }
    }
}

extern "C" void kernel_launch(void* const* d_in, const int* in_sizes, int n_in,
                              void* d_out, int out_size) {
    (void)in_sizes; (void)n_in; (void)out_size;
    const float* ts    = (const float*)d_in[0];
    const float* W0    = (const float*)d_in[1];
    const float* b0    = (const float*)d_in[2];
    const float* Wh    = (const float*)d_in[3];
    const float* bh    = (const float*)d_in[4];
    const float* Wl    = (const float*)d_in[5];
    const float* bl    = (const float*)d_in[6];
    const float* bW    = (const float*)d_in[7];
    const float* bb    = (const float*)d_in[8];
    const float* hvec  = (const float*)d_in[9];
    const float* scale = (const float*)d_in[10];
    const float* y0log = (const float*)d_in[11];
    float* out = (float*)d_out;

    reset_kernel<<<1, 1>>>();
    ode_kernel<<<NGRID, TPB>>>(ts, W0, b0, Wh, bh, Wl, bl, bW, bb,
                               hvec, scale, y0log, out);
}

// round 15
// speedup vs baseline: 1.4496x; 1.4496x over previous
#include <cuda_runtime.h>

#define TPB   288
#define NGRID 144          // g0:32  g1-g3:32 each  g4:16
#define WID   1024
#define HID   256
#define NST   17
#define NY    273
#define T_N   64
#define SUB   8
#define NSTAGE 2016

// ---------------- global scratch (no allocs) ----------------
__device__ __align__(16) float g_zb[4][WID];   // z0..z3 (single-buffered, ring-safe)
__device__ __align__(16) float g_dh[HID];      // final-layer output (scaled)
__device__ unsigned g_lnk[5 * 32];             // 5 link counters, one line each

__device__ __forceinline__ unsigned ld_acq(unsigned* p) {
    unsigned v;
    asm volatile("ld.acquire.gpu.global.u32 %0, [%1];" : "=r"(v) : "l"(p) : "memory");
    return v;
}
__device__ __forceinline__ void red_rel(unsigned* p) {
    asm volatile("red.release.gpu.global.add.u32 [%0], %1;" :: "l"(p), "r"(1u) : "memory");
}
// laws (R6/R13/R14): ONE acquire-poller per CTA, ONE release-RED per CTA.
__device__ __forceinline__ void wait1(int l, unsigned tgt) {
    unsigned* p = &g_lnk[l * 32];
    unsigned v;
    do { v = ld_acq(p); } while ((int)(v - tgt) < 0);
}

__device__ __forceinline__ float softplus_f(float v) {
    return fmaxf(v, 0.f) + log1pf(expf(-fabsf(v)));
}
__device__ __forceinline__ float warp_sum(float a) {
#pragma unroll
    for (int o = 16; o > 0; o >>= 1) a += __shfl_xor_sync(0xffffffffu, a, o);
    return a;
}
// 4-row reduce: lane j (j<4) holds full sum of row j
__device__ __forceinline__ float reduce4(float a0, float a1, float a2, float a3,
                                         int lane) {
    a0 += __shfl_xor_sync(0xffffffffu, a0, 1);
    a1 += __shfl_xor_sync(0xffffffffu, a1, 1);
    a2 += __shfl_xor_sync(0xffffffffu, a2, 1);
    a3 += __shfl_xor_sync(0xffffffffu, a3, 1);
    a0 += __shfl_xor_sync(0xffffffffu, a0, 2);
    a1 += __shfl_xor_sync(0xffffffffu, a1, 2);
    a2 += __shfl_xor_sync(0xffffffffu, a2, 2);
    a3 += __shfl_xor_sync(0xffffffffu, a3, 2);
    float v = (lane & 2) ? ((lane & 1) ? a3 : a2) : ((lane & 1) ? a1 : a0);
    v += __shfl_xor_sync(0xffffffffu, v, 4);
    v += __shfl_xor_sync(0xffffffffu, v, 8);
    v += __shfl_xor_sync(0xffffffffu, v, 16);
    return v;
}
// 2-row reduce: lane j (j<2) holds full sum of row j
__device__ __forceinline__ float reduce2(float a0, float a1, int lane) {
    a0 += __shfl_xor_sync(0xffffffffu, a0, 1);
    a1 += __shfl_xor_sync(0xffffffffu, a1, 1);
    float v = (lane & 1) ? a1 : a0;
    v += __shfl_xor_sync(0xffffffffu, v, 2);
    v += __shfl_xor_sync(0xffffffffu, v, 4);
    v += __shfl_xor_sync(0xffffffffu, v, 8);
    v += __shfl_xor_sync(0xffffffffu, v, 16);
    return v;
}

__global__ void reset_kernel() {
    for (int i = 0; i < 5; i++) g_lnk[i * 32] = 0u;
}

__global__ void __launch_bounds__(TPB, 1)
ode_kernel(const float* __restrict__ ts,  const float* __restrict__ W0,
           const float* __restrict__ b0,  const float* __restrict__ Wh,
           const float* __restrict__ bh,  const float* __restrict__ Wl,
           const float* __restrict__ bl,  const float* __restrict__ bW,
           const float* __restrict__ bb,  const float* __restrict__ hvec,
           const float* __restrict__ scale, const float* __restrict__ y0log,
           float* __restrict__ out)
{
    const int tid  = threadIdx.x;
    const int b    = blockIdx.x;
    const int warp = tid >> 5;
    const int lane = tid & 31;

    if (b < 32) {
        // ═════════ GROUP 0: inline x-build + layer0 + SEIR + state owner ═════════
        __shared__ float sy[NST + HID];    // [state(17) | h(256)], persistent
        __shared__ float skb[2][NST];      // SEIR slopes, stage-parity buffered
        const int lb = b;

        float w0r[4][9];                   // MLP warps: rows lb*32+warp*4+r
        float sbwr[8];                     // SEIR warp: bW chunks
        float breg = 0.f;
        const float bbv = __ldg(&bb[0]);

        if (warp < 8) {
#pragma unroll
            for (int r = 0; r < 4; r++)
#pragma unroll
                for (int i = 0; i < 9; i++) {
                    int col = lane + 32 * i;
                    int row = lb * 32 + warp * 4 + r;
                    w0r[r][i] = (col < 273) ? __ldg(&W0[row * 273 + col]) : 0.f;
                }
            if (lane < 4) breg = __ldg(&b0[lb * 32 + warp * 4 + lane]);
            sy[NST + warp * 32 + lane] = __ldg(&hvec[warp * 32 + lane]);
        } else {
#pragma unroll
            for (int i = 0; i < 8; i++) sbwr[i] = __ldg(&bW[lane + 32 * i]);
            if (lane == 0) {
                float m = -1e30f;
                for (int i = 0; i < NST; i++) m = fmaxf(m, __ldg(&y0log[i]));
                float s = 0.f, e[NST];
                for (int i = 0; i < NST; i++) { e[i] = expf(__ldg(&y0log[i]) - m); s += e[i]; }
                for (int i = 0; i < NST; i++) sy[i] = e[i] / s;
            }
        }
        __syncthreads();

        if (b == 0) {                      // output row 0
            if (warp < 8) out[T_N * NST + warp * 32 + lane] = sy[NST + warp * 32 + lane];
            else if (lane < NST) out[lane] = sy[lane];
        }

        const int hidx = warp * 32 + lane;
        float k1 = 0.f, k2 = 0.f, k3 = 0.f;

        for (int iv = 0; iv < T_N - 1; ++iv) {
            float dt  = (__ldg(&ts[iv + 1]) - __ldg(&ts[iv])) * (1.f / (float)SUB);
            float dt6 = dt * (1.f / 6.f);
            for (int ss = 0; ss < SUB; ++ss) {
                const unsigned base = 4u * (unsigned)(iv * SUB + ss);
#pragma unroll
                for (int st = 0; st < 4; ++st) {
                    const unsigned p = base + st;
                    const float c = (st == 0) ? 0.f : ((st == 3) ? dt : 0.5f * dt);
                    if (st > 0) {
                        if (tid == 0) wait1(4, 16u * p);
                        __syncthreads();
                    }

                    if (warp < 8) {
                        // ---- inline x-build + layer0 (4 rows/warp) ----
                        float xv[9];
                        float kp = 0.f;
#pragma unroll
                        for (int i = 0; i < 8; i++) {
                            int j = lane + 32 * i;
                            float dv = (st > 0) ? __ldcg(&g_dh[j]) : 0.f;
                            if (i == warp) kp = dv;
                            xv[i] = fmaf(c, dv, sy[NST + j]);
                        }
                        xv[8] = 0.f;
                        if (lane < NST) {
                            float sv = (st > 0) ? skb[(p - 1) & 1][lane] : 0.f;
                            xv[8] = fmaf(c, sv, sy[lane]);
                        }
                        if (st == 1) k1 = kp; else if (st == 2) k2 = kp;
                        else if (st == 3) k3 = kp;

                        float a0 = 0.f, a1 = 0.f, a2 = 0.f, a3 = 0.f;
#pragma unroll
                        for (int i = 0; i < 9; i++) {
                            a0 = fmaf(w0r[0][i], xv[i], a0);
                            a1 = fmaf(w0r[1][i], xv[i], a1);
                            a2 = fmaf(w0r[2][i], xv[i], a2);
                            a3 = fmaf(w0r[3][i], xv[i], a3);
                        }
                        float v = reduce4(a0, a1, a2, a3, lane);
                        if (lane < 4)
                            __stcg(&g_zb[0][lb * 32 + warp * 4 + lane],
                                   softplus_f(v + breg));
                    } else {
                        // ---- SEIR warp: slopes into parity smem buffer ----
                        float t = 0.f;
#pragma unroll
                        for (int i = 0; i < 8; i++) {
                            int j = lane + 32 * i;
                            float hv = sy[NST + j];
                            if (st > 0) hv = fmaf(c, __ldcg(&g_dh[j]), hv);
                            t = fmaf(sbwr[i], hv, t);
                        }
                        t = warp_sum(t);
                        if (st > 0 && lane < NST) {
                            float v = skb[(p - 1) & 1][lane];
                            if (st == 1) k1 = v; else if (st == 2) k2 = v; else k3 = v;
                        }
                        if (lane == 0) {
                            float bb1 = 8.f / (1.f + expf(-(t + bbv))) + 25.f;
                            float s_[NST];
#pragma unroll
                            for (int L = 0; L < NST; L++)
                                s_[L] = (st > 0) ? fmaf(c, skb[(p - 1) & 1][L], sy[L])
                                                 : sy[L];
                            const float MU   = (float)(0.041 / 12.0);
                            const float XI   = (float)(13.0 / 12.0);
                            const float XIMU = (float)(13.0 / 12.0 + 0.041 / 12.0);
                            const float MUSG = (float)(0.041 / 12.0 + 91.0 / 12.0);
                            const float SG   = (float)(91.0 / 12.0);
                            const float NU   = (float)(36.0 / 12.0);
                            const float NUMU = (float)(36.0 / 12.0 + 0.041 / 12.0);
                            const float MUGA = (float)(0.041 / 12.0 + 1.8 / 12.0);
                            const float GA   = (float)(1.8 / 12.0);
                            float M  = s_[0],  S1 = s_[1],  E1 = s_[2],  E2 = s_[3];
                            float E3 = s_[4],  E4 = s_[5],  I1 = s_[6],  I2 = s_[7];
                            float I3 = s_[8],  I4 = s_[9],  R1 = s_[10], R2 = s_[11];
                            float R3 = s_[12], R4 = s_[13], S2 = s_[14], S3 = s_[15];
                            float S4 = s_[16];
                            float I = I1 + I2 + I3 + I4;
                            float R = R1 + R2 + R3 + R4;
                            float bb2 = 0.5f * bb1, bb3 = 0.35f * bb1, bb4 = 0.25f * bb1;
                            skb[p & 1][0]  = R * MU - XIMU * M;
                            skb[p & 1][1]  = MU * (1.f - R) + XI * M - MU * S1 - bb1 * I * S1;
                            skb[p & 1][2]  = bb1 * I * S1 - MUSG * E1;
                            skb[p & 1][3]  = bb2 * I * S2 - MUSG * E2;
                            skb[p & 1][4]  = bb3 * I * S3 - MUSG * E3;
                            skb[p & 1][5]  = bb4 * I * S4 - MUSG * E4;
                            skb[p & 1][6]  = SG * E1 - NUMU * I1;
                            skb[p & 1][7]  = SG * E2 - NUMU * I2;
                            skb[p & 1][8]  = SG * E3 - NUMU * I3;
                            skb[p & 1][9]  = SG * E4 - NUMU * I4;
                            skb[p & 1][10] = NU * I1 - MUGA * R1;
                            skb[p & 1][11] = NU * I2 - MUGA * R2;
                            skb[p & 1][12] = NU * I3 - MUGA * R3;
                            skb[p & 1][13] = NU * I4 - MUGA * R4;
                            skb[p & 1][14] = GA * R1 - MU * S2 - bb2 * I * S2;
                            skb[p & 1][15] = GA * R2 - MU * S3 - bb3 * I * S3;
                            skb[p & 1][16] = GA * (R3 + R4) - MU * S4 - bb4 * I * S4;
                        }
                    }
                    __syncthreads();                    // all z0 stores + skb done
                    if (tid == 0) red_rel(&g_lnk[0]);   // one release per CTA
                } // st

                // ---- substep boundary: RK combine on smem sy ----
                if (tid == 0) wait1(4, 16u * (base + 4u));
                __syncthreads();
                if (warp < 8) {
                    float k4 = __ldcg(&g_dh[hidx]);
                    float yn = fmaf(dt6, k1 + 2.f * (k2 + k3) + k4, sy[NST + hidx]);
                    sy[NST + hidx] = yn;
                    if (b == 0 && ss == SUB - 1)
                        out[T_N * NST + (iv + 1) * HID + hidx] = yn;
                } else if (lane < NST) {
                    float k4 = skb[(base + 3u) & 1][lane];
                    float yn = fmaf(dt6, k1 + 2.f * (k2 + k3) + k4, sy[lane]);
                    sy[lane] = yn;
                    if (b == 0 && ss == SUB - 1)
                        out[(iv + 1) * NST + lane] = yn;
                }
                __syncthreads();
            } // ss
        } // iv

    } else if (b < 128) {
        // ═════ GROUPS 1-3: hidden layers (thread0 poll, direct reg fetch,
        //                   CTA-level publish) ═════
        const int hl = (b >> 5) - 1;
        const int lb = b & 31;
        if (warp >= 8) return;
        float4 wt[4][8];
#pragma unroll
        for (int r = 0; r < 4; r++)
#pragma unroll
            for (int i = 0; i < 8; i++)
                wt[r][i] = __ldg((const float4*)&Wh[((hl * WID) + (lb * 32 + warp * 4 + r))
                                                    * WID + lane * 4 + 128 * i]);
        float breg = (lane < 4) ? __ldg(&bh[hl * WID + lb * 32 + warp * 4 + lane]) : 0.f;

        for (unsigned it = 1; it <= NSTAGE; ++it) {
            if (tid == 0) wait1(hl, 32u * it);
            __syncthreads();
            float a0 = 0.f, a1 = 0.f, a2 = 0.f, a3 = 0.f;
#pragma unroll
            for (int i = 0; i < 8; i++) {
                float4 z = __ldcg((const float4*)&g_zb[hl][(lane + 32 * i) * 4]);
                float4 q;
                q = wt[0][i];
                a0 = fmaf(q.x, z.x, a0); a0 = fmaf(q.y, z.y, a0);
                a0 = fmaf(q.z, z.z, a0); a0 = fmaf(q.w, z.w, a0);
                q = wt[1][i];
                a1 = fmaf(q.x, z.x, a1); a1 = fmaf(q.y, z.y, a1);
                a1 = fmaf(q.z, z.z, a1); a1 = fmaf(q.w, z.w, a1);
                q = wt[2][i];
                a2 = fmaf(q.x, z.x, a2); a2 = fmaf(q.y, z.y, a2);
                a2 = fmaf(q.z, z.z, a2); a2 = fmaf(q.w, z.w, a2);
                q = wt[3][i];
                a3 = fmaf(q.x, z.x, a3); a3 = fmaf(q.y, z.y, a3);
                a3 = fmaf(q.z, z.z, a3); a3 = fmaf(q.w, z.w, a3);
            }
            float v = reduce4(a0, a1, a2, a3, lane);
            if (lane < 4)
                __stcg(&g_zb[hl + 1][lb * 32 + warp * 4 + lane],
                       softplus_f(v + breg));
            __syncthreads();
            if (tid == 0) red_rel(&g_lnk[(hl + 1) * 32]);
        }

    } else {
        // ═════ GROUP 4: final layer (thread0 poll, direct reg fetch,
        //               CTA-level publish) ═════
        const int lb = b - 128;
        if (warp >= 8) return;
        float4 wt[2][8];
#pragma unroll
        for (int r = 0; r < 2; r++)
#pragma unroll
            for (int i = 0; i < 8; i++)
                wt[r][i] = __ldg((const float4*)&Wl[(lb * 16 + warp * 2 + r) * WID
                                                    + lane * 4 + 128 * i]);
        float breg = (lane < 2) ? __ldg(&bl[lb * 16 + warp * 2 + lane]) : 0.f;
        const float scl = __ldg(&scale[0]);

        for (unsigned it = 1; it <= NSTAGE; ++it) {
            if (tid == 0) wait1(3, 32u * it);
            __syncthreads();
            float a0 = 0.f, a1 = 0.f;
#pragma unroll
            for (int i = 0; i < 8; i++) {
                float4 z = __ldcg((const float4*)&g_zb[3][(lane + 32 * i) * 4]);
                float4 q;
                q = wt[0][i];
                a0 = fmaf(q.x, z.x, a0); a0 = fmaf(q.y, z.y, a0);
                a0 = fmaf(q.z, z.z, a0); a0 = fmaf(q.w, z.w, a0);
                q = wt[1][i];
                a1 = fmaf(q.x, z.x, a1); a1 = fmaf(q.y, z.y, a1);
                a1 = fmaf(q.z, z.z, a1); a1 = fmaf(q.w, z.w, a1);
            }
            float v = reduce2(a0, a1, lane);
            if (lane < 2) {
                float u = tanhf(0.01f * (v + breg));
                __stcg(&g_dh[lb * 16 + warp * 2 + lane], scl * u);
            }
            __syncthreads();
            if (tid == 0) red_rel(&g_lnk[4 * 32]);
        }
    }
}

extern "C" void kernel_launch(void* const* d_in, const int* in_sizes, int n_in,
                              void* d_out, int out_size) {
    (void)in_sizes; (void)n_in; (void)out_size;
    const float* ts    = (const float*)d_in[0];
    const float* W0    = (const float*)d_in[1];
    const float* b0    = (const float*)d_in[2];
    const float* Wh    = (const float*)d_in[3];
    const float* bh    = (const float*)d_in[4];
    const float* Wl    = (const float*)d_in[5];
    const float* bl    = (const float*)d_in[6];
    const float* bW    = (const float*)d_in[7];
    const float* bb    = (const float*)d_in[8];
    const float* hvec  = (const float*)d_in[9];
    const float* scale = (const float*)d_in[10];
    const float* y0log = (const float*)d_in[11];
    float* out = (float*)d_out;

    reset_kernel<<<1, 1>>>();
    ode_kernel<<<NGRID, TPB>>>(ts, W0, b0, Wh, bh, Wl, bl, bW, bb,
                               hvec, scale, y0log, out);
}

// round 16
// speedup vs baseline: 1.6509x; 1.1389x over previous
#include <cuda_runtime.h>

#define TPB   288
#define NGRID 144          // g0:32  g1-g3:32 each  g4:16
#define WID   1024
#define HID   256
#define NST   17
#define NY    273
#define T_N   64
#define SUB   8
#define NSTAGE 2016

// ---------------- global scratch (no allocs) ----------------
__device__ __align__(16) float g_zb[4][WID];   // z0..z3 (single-buffered, ring-safe)
__device__ __align__(16) float g_dh[HID];      // final-layer output (scaled)
__device__ unsigned g_lnk[5 * 32];             // 5 link counters, one line each

__device__ __forceinline__ unsigned ld_acq(unsigned* p) {
    unsigned v;
    asm volatile("ld.acquire.gpu.global.u32 %0, [%1];" : "=r"(v) : "l"(p) : "memory");
    return v;
}
__device__ __forceinline__ void red_rel(unsigned* p) {
    asm volatile("red.release.gpu.global.add.u32 [%0], %1;" :: "l"(p), "r"(1u) : "memory");
}
// laws: ONE acquire-poller per CTA (R6/R13), ONE release-RED per CTA (R14/R15),
// fan shared vectors through smem — one global read per CTA (R14/R15).
__device__ __forceinline__ void wait1(int l, unsigned tgt) {
    unsigned* p = &g_lnk[l * 32];
    unsigned v;
    do { v = ld_acq(p); } while ((int)(v - tgt) < 0);
}

__device__ __forceinline__ float softplus_f(float v) {
    return fmaxf(v, 0.f) + log1pf(expf(-fabsf(v)));
}
__device__ __forceinline__ float warp_sum(float a) {
#pragma unroll
    for (int o = 16; o > 0; o >>= 1) a += __shfl_xor_sync(0xffffffffu, a, o);
    return a;
}
// 4-row reduce: lane j (j<4) holds full sum of row j
__device__ __forceinline__ float reduce4(float a0, float a1, float a2, float a3,
                                         int lane) {
    a0 += __shfl_xor_sync(0xffffffffu, a0, 1);
    a1 += __shfl_xor_sync(0xffffffffu, a1, 1);
    a2 += __shfl_xor_sync(0xffffffffu, a2, 1);
    a3 += __shfl_xor_sync(0xffffffffu, a3, 1);
    a0 += __shfl_xor_sync(0xffffffffu, a0, 2);
    a1 += __shfl_xor_sync(0xffffffffu, a1, 2);
    a2 += __shfl_xor_sync(0xffffffffu, a2, 2);
    a3 += __shfl_xor_sync(0xffffffffu, a3, 2);
    float v = (lane & 2) ? ((lane & 1) ? a3 : a2) : ((lane & 1) ? a1 : a0);
    v += __shfl_xor_sync(0xffffffffu, v, 4);
    v += __shfl_xor_sync(0xffffffffu, v, 8);
    v += __shfl_xor_sync(0xffffffffu, v, 16);
    return v;
}
// 2-row reduce: lane j (j<2) holds full sum of row j
__device__ __forceinline__ float reduce2(float a0, float a1, int lane) {
    a0 += __shfl_xor_sync(0xffffffffu, a0, 1);
    a1 += __shfl_xor_sync(0xffffffffu, a1, 1);
    float v = (lane & 1) ? a1 : a0;
    v += __shfl_xor_sync(0xffffffffu, v, 2);
    v += __shfl_xor_sync(0xffffffffu, v, 4);
    v += __shfl_xor_sync(0xffffffffu, v, 8);
    v += __shfl_xor_sync(0xffffffffu, v, 16);
    return v;
}

__global__ void reset_kernel() {
    for (int i = 0; i < 5; i++) g_lnk[i * 32] = 0u;
}

__global__ void __launch_bounds__(TPB, 1)
ode_kernel(const float* __restrict__ ts,  const float* __restrict__ W0,
           const float* __restrict__ b0,  const float* __restrict__ Wh,
           const float* __restrict__ bh,  const float* __restrict__ Wl,
           const float* __restrict__ bl,  const float* __restrict__ bW,
           const float* __restrict__ bb,  const float* __restrict__ hvec,
           const float* __restrict__ scale, const float* __restrict__ y0log,
           float* __restrict__ out)
{
    const int tid  = threadIdx.x;
    const int b    = blockIdx.x;
    const int warp = tid >> 5;
    const int lane = tid & 31;

    if (b < 32) {
        // ═════════ GROUP 0: inline x-build + layer0 + SEIR + state owner ═════════
        __shared__ float sy[NST + HID];    // [state(17) | h(256)], persistent
        __shared__ float skb[2][NST];      // SEIR slopes, stage-parity buffered
        const int lb = b;

        float w0r[4][9];
        float sbwr[8];
        float breg = 0.f;
        const float bbv = __ldg(&bb[0]);

        if (warp < 8) {
#pragma unroll
            for (int r = 0; r < 4; r++)
#pragma unroll
                for (int i = 0; i < 9; i++) {
                    int col = lane + 32 * i;
                    int row = lb * 32 + warp * 4 + r;
                    w0r[r][i] = (col < 273) ? __ldg(&W0[row * 273 + col]) : 0.f;
                }
            if (lane < 4) breg = __ldg(&b0[lb * 32 + warp * 4 + lane]);
            sy[NST + warp * 32 + lane] = __ldg(&hvec[warp * 32 + lane]);
        } else {
#pragma unroll
            for (int i = 0; i < 8; i++) sbwr[i] = __ldg(&bW[lane + 32 * i]);
            if (lane == 0) {
                float m = -1e30f;
                for (int i = 0; i < NST; i++) m = fmaxf(m, __ldg(&y0log[i]));
                float s = 0.f, e[NST];
                for (int i = 0; i < NST; i++) { e[i] = expf(__ldg(&y0log[i]) - m); s += e[i]; }
                for (int i = 0; i < NST; i++) sy[i] = e[i] / s;
            }
        }
        __syncthreads();

        if (b == 0) {                      // output row 0
            if (warp < 8) out[T_N * NST + warp * 32 + lane] = sy[NST + warp * 32 + lane];
            else if (lane < NST) out[lane] = sy[lane];
        }

        const int hidx = warp * 32 + lane;
        float k1 = 0.f, k2 = 0.f, k3 = 0.f;

        for (int iv = 0; iv < T_N - 1; ++iv) {
            float dt  = (__ldg(&ts[iv + 1]) - __ldg(&ts[iv])) * (1.f / (float)SUB);
            float dt6 = dt * (1.f / 6.f);
            for (int ss = 0; ss < SUB; ++ss) {
                const unsigned base = 4u * (unsigned)(iv * SUB + ss);
#pragma unroll
                for (int st = 0; st < 4; ++st) {
                    const unsigned p = base + st;
                    const float c = (st == 0) ? 0.f : ((st == 3) ? dt : 0.5f * dt);
                    if (st > 0) {
                        if (tid == 0) wait1(4, 16u * p);
                        __syncthreads();
                    }

                    if (warp < 8) {
                        // ---- inline x-build + layer0 (4 rows/warp) ----
                        float xv[9];
                        float kp = 0.f;
#pragma unroll
                        for (int i = 0; i < 8; i++) {
                            int j = lane + 32 * i;
                            float dv = (st > 0) ? __ldcg(&g_dh[j]) : 0.f;
                            if (i == warp) kp = dv;
                            xv[i] = fmaf(c, dv, sy[NST + j]);
                        }
                        xv[8] = 0.f;
                        if (lane < NST) {
                            float sv = (st > 0) ? skb[(p - 1) & 1][lane] : 0.f;
                            xv[8] = fmaf(c, sv, sy[lane]);
                        }
                        if (st == 1) k1 = kp; else if (st == 2) k2 = kp;
                        else if (st == 3) k3 = kp;

                        float a0 = 0.f, a1 = 0.f, a2 = 0.f, a3 = 0.f;
#pragma unroll
                        for (int i = 0; i < 9; i++) {
                            a0 = fmaf(w0r[0][i], xv[i], a0);
                            a1 = fmaf(w0r[1][i], xv[i], a1);
                            a2 = fmaf(w0r[2][i], xv[i], a2);
                            a3 = fmaf(w0r[3][i], xv[i], a3);
                        }
                        float v = reduce4(a0, a1, a2, a3, lane);
                        if (lane < 4)
                            __stcg(&g_zb[0][lb * 32 + warp * 4 + lane],
                                   softplus_f(v + breg));
                    } else {
                        // ---- SEIR warp: slopes into parity smem buffer ----
                        float t = 0.f;
#pragma unroll
                        for (int i = 0; i < 8; i++) {
                            int j = lane + 32 * i;
                            float hv = sy[NST + j];
                            if (st > 0) hv = fmaf(c, __ldcg(&g_dh[j]), hv);
                            t = fmaf(sbwr[i], hv, t);
                        }
                        t = warp_sum(t);
                        if (st > 0 && lane < NST) {
                            float v = skb[(p - 1) & 1][lane];
                            if (st == 1) k1 = v; else if (st == 2) k2 = v; else k3 = v;
                        }
                        if (lane == 0) {
                            float bb1 = 8.f / (1.f + expf(-(t + bbv))) + 25.f;
                            float s_[NST];
#pragma unroll
                            for (int L = 0; L < NST; L++)
                                s_[L] = (st > 0) ? fmaf(c, skb[(p - 1) & 1][L], sy[L])
                                                 : sy[L];
                            const float MU   = (float)(0.041 / 12.0);
                            const float XI   = (float)(13.0 / 12.0);
                            const float XIMU = (float)(13.0 / 12.0 + 0.041 / 12.0);
                            const float MUSG = (float)(0.041 / 12.0 + 91.0 / 12.0);
                            const float SG   = (float)(91.0 / 12.0);
                            const float NU   = (float)(36.0 / 12.0);
                            const float NUMU = (float)(36.0 / 12.0 + 0.041 / 12.0);
                            const float MUGA = (float)(0.041 / 12.0 + 1.8 / 12.0);
                            const float GA   = (float)(1.8 / 12.0);
                            float M  = s_[0],  S1 = s_[1],  E1 = s_[2],  E2 = s_[3];
                            float E3 = s_[4],  E4 = s_[5],  I1 = s_[6],  I2 = s_[7];
                            float I3 = s_[8],  I4 = s_[9],  R1 = s_[10], R2 = s_[11];
                            float R3 = s_[12], R4 = s_[13], S2 = s_[14], S3 = s_[15];
                            float S4 = s_[16];
                            float I = I1 + I2 + I3 + I4;
                            float R = R1 + R2 + R3 + R4;
                            float bb2 = 0.5f * bb1, bb3 = 0.35f * bb1, bb4 = 0.25f * bb1;
                            skb[p & 1][0]  = R * MU - XIMU * M;
                            skb[p & 1][1]  = MU * (1.f - R) + XI * M - MU * S1 - bb1 * I * S1;
                            skb[p & 1][2]  = bb1 * I * S1 - MUSG * E1;
                            skb[p & 1][3]  = bb2 * I * S2 - MUSG * E2;
                            skb[p & 1][4]  = bb3 * I * S3 - MUSG * E3;
                            skb[p & 1][5]  = bb4 * I * S4 - MUSG * E4;
                            skb[p & 1][6]  = SG * E1 - NUMU * I1;
                            skb[p & 1][7]  = SG * E2 - NUMU * I2;
                            skb[p & 1][8]  = SG * E3 - NUMU * I3;
                            skb[p & 1][9]  = SG * E4 - NUMU * I4;
                            skb[p & 1][10] = NU * I1 - MUGA * R1;
                            skb[p & 1][11] = NU * I2 - MUGA * R2;
                            skb[p & 1][12] = NU * I3 - MUGA * R3;
                            skb[p & 1][13] = NU * I4 - MUGA * R4;
                            skb[p & 1][14] = GA * R1 - MU * S2 - bb2 * I * S2;
                            skb[p & 1][15] = GA * R2 - MU * S3 - bb3 * I * S3;
                            skb[p & 1][16] = GA * (R3 + R4) - MU * S4 - bb4 * I * S4;
                        }
                    }
                    __syncthreads();                    // z0 stores + skb done
                    if (tid == 0) red_rel(&g_lnk[0]);   // one release per CTA
                } // st

                // ---- substep boundary: RK combine on smem sy ----
                if (tid == 0) wait1(4, 16u * (base + 4u));
                __syncthreads();
                if (warp < 8) {
                    float k4 = __ldcg(&g_dh[hidx]);
                    float yn = fmaf(dt6, k1 + 2.f * (k2 + k3) + k4, sy[NST + hidx]);
                    sy[NST + hidx] = yn;
                    if (b == 0 && ss == SUB - 1)
                        out[T_N * NST + (iv + 1) * HID + hidx] = yn;
                } else if (lane < NST) {
                    float k4 = skb[(base + 3u) & 1][lane];
                    float yn = fmaf(dt6, k1 + 2.f * (k2 + k3) + k4, sy[lane]);
                    sy[lane] = yn;
                    if (b == 0 && ss == SUB - 1)
                        out[(iv + 1) * NST + lane] = yn;
                }
                __syncthreads();
            } // ss
        } // iv

    } else if (b < 128) {
        // ═════ GROUPS 1-3: hidden layers — smem-staged fetch (one global
        //       read per CTA), CTA-level publish ═════
        __shared__ __align__(16) float szf[WID];
        const int hl = (b >> 5) - 1;
        const int lb = b & 31;
        if (warp >= 8) return;           // 8 warps (256 thr) remain
        float4 wt[4][8];
#pragma unroll
        for (int r = 0; r < 4; r++)
#pragma unroll
            for (int i = 0; i < 8; i++)
                wt[r][i] = __ldg((const float4*)&Wh[((hl * WID) + (lb * 32 + warp * 4 + r))
                                                    * WID + lane * 4 + 128 * i]);
        float breg = (lane < 4) ? __ldg(&bh[hl * WID + lb * 32 + warp * 4 + lane]) : 0.f;

        for (unsigned it = 1; it <= NSTAGE; ++it) {
            if (tid == 0) wait1(hl, 32u * it);
            __syncthreads();             // detect + WAR on szf
            ((float4*)szf)[tid] = __ldcg((const float4*)&g_zb[hl][tid * 4]);
            __syncthreads();
            float a0 = 0.f, a1 = 0.f, a2 = 0.f, a3 = 0.f;
            const float4* z4 = (const float4*)szf;
#pragma unroll
            for (int i = 0; i < 8; i++) {
                float4 z = z4[lane + 32 * i];
                float4 q;
                q = wt[0][i];
                a0 = fmaf(q.x, z.x, a0); a0 = fmaf(q.y, z.y, a0);
                a0 = fmaf(q.z, z.z, a0); a0 = fmaf(q.w, z.w, a0);
                q = wt[1][i];
                a1 = fmaf(q.x, z.x, a1); a1 = fmaf(q.y, z.y, a1);
                a1 = fmaf(q.z, z.z, a1); a1 = fmaf(q.w, z.w, a1);
                q = wt[2][i];
                a2 = fmaf(q.x, z.x, a2); a2 = fmaf(q.y, z.y, a2);
                a2 = fmaf(q.z, z.z, a2); a2 = fmaf(q.w, z.w, a2);
                q = wt[3][i];
                a3 = fmaf(q.x, z.x, a3); a3 = fmaf(q.y, z.y, a3);
                a3 = fmaf(q.z, z.z, a3); a3 = fmaf(q.w, z.w, a3);
            }
            float v = reduce4(a0, a1, a2, a3, lane);
            if (lane < 4)
                __stcg(&g_zb[hl + 1][lb * 32 + warp * 4 + lane],
                       softplus_f(v + breg));
            __syncthreads();             // all warps' stores done
            if (tid == 0) red_rel(&g_lnk[(hl + 1) * 32]);
        }

    } else {
        // ═════ GROUP 4: final layer — smem-staged fetch, CTA-level publish ═════
        __shared__ __align__(16) float szf[WID];
        const int lb = b - 128;
        if (warp >= 8) return;
        float4 wt[2][8];
#pragma unroll
        for (int r = 0; r < 2; r++)
#pragma unroll
            for (int i = 0; i < 8; i++)
                wt[r][i] = __ldg((const float4*)&Wl[(lb * 16 + warp * 2 + r) * WID
                                                    + lane * 4 + 128 * i]);
        float breg = (lane < 2) ? __ldg(&bl[lb * 16 + warp * 2 + lane]) : 0.f;
        const float scl = __ldg(&scale[0]);

        for (unsigned it = 1; it <= NSTAGE; ++it) {
            if (tid == 0) wait1(3, 32u * it);
            __syncthreads();
            ((float4*)szf)[tid] = __ldcg((const float4*)&g_zb[3][tid * 4]);
            __syncthreads();
            float a0 = 0.f, a1 = 0.f;
            const float4* z4 = (const float4*)szf;
#pragma unroll
            for (int i = 0; i < 8; i++) {
                float4 z = z4[lane + 32 * i];
                float4 q;
                q = wt[0][i];
                a0 = fmaf(q.x, z.x, a0); a0 = fmaf(q.y, z.y, a0);
                a0 = fmaf(q.z, z.z, a0); a0 = fmaf(q.w, z.w, a0);
                q = wt[1][i];
                a1 = fmaf(q.x, z.x, a1); a1 = fmaf(q.y, z.y, a1);
                a1 = fmaf(q.z, z.z, a1); a1 = fmaf(q.w, z.w, a1);
            }
            float v = reduce2(a0, a1, lane);
            if (lane < 2) {
                float u = tanhf(0.01f * (v + breg));
                __stcg(&g_dh[lb * 16 + warp * 2 + lane], scl * u);
            }
            __syncthreads();
            if (tid == 0) red_rel(&g_lnk[4 * 32]);
        }
    }
}

extern "C" void kernel_launch(void* const* d_in, const int* in_sizes, int n_in,
                              void* d_out, int out_size) {
    (void)in_sizes; (void)n_in; (void)out_size;
    const float* ts    = (const float*)d_in[0];
    const float* W0    = (const float*)d_in[1];
    const float* b0    = (const float*)d_in[2];
    const float* Wh    = (const float*)d_in[3];
    const float* bh    = (const float*)d_in[4];
    const float* Wl    = (const float*)d_in[5];
    const float* bl    = (const float*)d_in[6];
    const float* bW    = (const float*)d_in[7];
    const float* bb    = (const float*)d_in[8];
    const float* hvec  = (const float*)d_in[9];
    const float* scale = (const float*)d_in[10];
    const float* y0log = (const float*)d_in[11];
    float* out = (float*)d_out;

    reset_kernel<<<1, 1>>>();
    ode_kernel<<<NGRID, TPB>>>(ts, W0, b0, Wh, bh, Wl, bl, bW, bb,
                               hvec, scale, y0log, out);
}